// round 16
// baseline (speedup 1.0000x reference)
#include <cuda_runtime.h>
#include <cuda_fp16.h>
#include <math.h>
#include <stdint.h>

// B=32, N=4096, D=512, K=64
#define Bb 32
#define Nn 4096
#define Dd 512
#define Kk 64
#define NSPLIT 4

__device__ __half g_xh[(size_t)Bb * Nn * Dd];              // x as half, [n][d] (written by k1)
__device__ __half g_ch[(size_t)Kk * Dd];                   // clusters^T half [k][d]
__device__ __half g_ah[(size_t)Bb * Kk * Nn];              // assignment^T half [b][k][n]
__device__ float  g_vpart[(size_t)NSPLIT * Bb * Kk * Dd];  // vlad partials [s,b,k,d]
__device__ float  g_asum[Bb * Kk];
__device__ float  g_gnormsq[Bb];

__device__ __forceinline__ uint32_t h2pack(float lo, float hi) {
    __half2 h = __floats2half2_rn(lo, hi);
    return *(uint32_t*)&h;
}

__device__ __forceinline__ void mma16(float* c, uint32_t a0, uint32_t a1,
                                      uint32_t a2, uint32_t a3,
                                      uint32_t b0, uint32_t b1) {
    asm volatile(
        "mma.sync.aligned.m16n8k16.row.col.f32.f16.f16.f32 "
        "{%0,%1,%2,%3},{%4,%5,%6,%7},{%8,%9},{%0,%1,%2,%3};\n"
        : "+f"(c[0]), "+f"(c[1]), "+f"(c[2]), "+f"(c[3])
        : "r"(a0), "r"(a1), "r"(a2), "r"(a3), "r"(b0), "r"(b1));
}

__device__ __forceinline__ void ldsm4t(uint32_t& r0, uint32_t& r1,
                                       uint32_t& r2, uint32_t& r3, uint32_t a) {
    asm volatile(
        "ldmatrix.sync.aligned.m8n8.x4.trans.shared.b16 {%0,%1,%2,%3}, [%4];"
        : "=r"(r0), "=r"(r1), "=r"(r2), "=r"(r3) : "r"(a));
}

__device__ __forceinline__ uint32_t smem_u32(const void* p) {
    uint32_t a;
    asm("{ .reg .u64 t; cvta.to.shared.u64 t, %1; cvt.u32.u64 %0, t; }"
        : "=r"(a) : "l"(p));
    return a;
}

#define CP16(dst, src) \
    asm volatile("cp.async.cg.shared.global [%0], [%1], 16;\n" \
                 :: "r"(dst), "l"(src) : "memory")
#define CP_COMMIT() asm volatile("cp.async.commit_group;\n" ::: "memory")
#define CP_WAIT1()  asm volatile("cp.async.wait_group 1;\n" ::: "memory")
#define CP_WAIT2()  asm volatile("cp.async.wait_group 2;\n" ::: "memory")

// ---------------------------------------------------------------------------
__global__ void k0_init() {
    int i = blockIdx.x * 256 + threadIdx.x;
    if (i < Bb * Kk) g_asum[i] = 0.0f;
    if (i < Bb)      g_gnormsq[i] = 0.0f;
}

// ---------------------------------------------------------------------------
// kC: clusters [d][k] fp32 -> g_ch [k][d] half
// ---------------------------------------------------------------------------
__global__ __launch_bounds__(256) void kC(const float* __restrict__ clusters) {
    int idx4 = (blockIdx.x * 256 + threadIdx.x) * 4;
    int d = idx4 >> 6, k = idx4 & 63;
    float4 c = *(const float4*)&clusters[idx4];
    g_ch[(size_t)(k + 0) * Dd + d] = __float2half_rn(c.x);
    g_ch[(size_t)(k + 1) * Dd + d] = __float2half_rn(c.y);
    g_ch[(size_t)(k + 2) * Dd + d] = __float2half_rn(c.z);
    g_ch[(size_t)(k + 3) * Dd + d] = __float2half_rn(c.w);
}

// ---------------------------------------------------------------------------
// k1: x fp32 in (2-stage cp.async) -> fp16 convert (smem + g_xh out),
// fp16 MMA + BN + softmax + assignment^T(half) + a_sum.  (unchanged from R15)
// ---------------------------------------------------------------------------
#define K1F_CS   18432
#define K1F_ST   23552
#define K1_XSH   47104
#define K1_SCF   57344
#define K1_SHF   57600
#define K1_RED   57856
#define K1_SMEM  59904

__device__ __forceinline__ void k1_issue(uint32_t sbase, const float* xg,
                                         int c, int tid) {
    if (c < 16) {
        uint32_t st = sbase + (c & 1) * K1F_ST;
        int d0 = c * 32;
#pragma unroll
        for (int p = 0; p < 4; p++) {
            int id = p * 256 + tid;
            int row = id >> 3, sq = id & 7;
            CP16(st + row * 144 + sq * 16,
                 xg + (size_t)row * Dd + d0 + sq * 4);
        }
        {
            int row = tid >> 2, sq = tid & 3;
            CP16(st + K1F_CS + row * 80 + sq * 16,
                 g_ch + (size_t)row * Dd + d0 + sq * 8);
        }
    }
    CP_COMMIT();
}

__global__ __launch_bounds__(256) void k1_logits_softmax(
    const float* __restrict__ x,
    const float* __restrict__ bnw,
    const float* __restrict__ bnb,
    const float* __restrict__ rm,
    const float* __restrict__ rv)
{
    extern __shared__ __align__(16) char sm[];
    float* scf = (float*)(sm + K1_SCF);
    float* shf = (float*)(sm + K1_SHF);
    float* red = (float*)(sm + K1_RED);
    uint32_t* xh32 = (uint32_t*)(sm + K1_XSH);
    const uint32_t sbase = smem_u32(sm);

    const int tid  = threadIdx.x;
    const int lane = tid & 31;
    const int w    = tid >> 5;
    const int la   = lane >> 2;
    const int lb   = lane & 3;
    const int row0 = blockIdx.x * 128;

    if (tid < 64) {
        float istd = rsqrtf(rv[tid] + 1e-5f);
        float s = bnw[tid] * istd;
        scf[tid] = s;
        shf[tid] = bnb[tid] - rm[tid] * s;
    }

    const float* xg = x + (size_t)row0 * Dd;

    float acc[8][4];
#pragma unroll
    for (int j = 0; j < 8; j++)
#pragma unroll
        for (int q = 0; q < 4; q++) acc[j][q] = 0.0f;

    k1_issue(sbase, xg, 0, tid);

    const int wr = w * 16 + la;
    const int crow = tid >> 1;
    const int ch   = tid & 1;

    for (int c = 0; c < 16; c++) {
        __syncthreads();
        k1_issue(sbase, xg, c + 1, tid);
        CP_WAIT1();
        __syncthreads();

        {
            const char* stx = sm + (c & 1) * K1F_ST;
            const float4* src = (const float4*)(stx + crow * 144 + ch * 64);
            float4 v0 = src[0], v1 = src[1], v2 = src[2], v3 = src[3];
            uint32_t wv[8];
            wv[0] = h2pack(v0.x, v0.y); wv[1] = h2pack(v0.z, v0.w);
            wv[2] = h2pack(v1.x, v1.y); wv[3] = h2pack(v1.z, v1.w);
            wv[4] = h2pack(v2.x, v2.y); wv[5] = h2pack(v2.z, v2.w);
            wv[6] = h2pack(v3.x, v3.y); wv[7] = h2pack(v3.z, v3.w);
            *(uint4*)&xh32[crow * 20 + ch * 8]     = make_uint4(wv[0], wv[1], wv[2], wv[3]);
            *(uint4*)&xh32[crow * 20 + ch * 8 + 4] = make_uint4(wv[4], wv[5], wv[6], wv[7]);
            __half* gd = g_xh + (size_t)(row0 + crow) * Dd + c * 32 + ch * 16;
            *(uint4*)gd       = make_uint4(wv[0], wv[1], wv[2], wv[3]);
            *(uint4*)(gd + 8) = make_uint4(wv[4], wv[5], wv[6], wv[7]);
        }
        __syncthreads();

        const uint32_t* csA = (const uint32_t*)(sm + (c & 1) * K1F_ST + K1F_CS);
#pragma unroll
        for (int s = 0; s < 2; s++) {
            uint32_t a0 = xh32[wr * 20 + s * 8 + lb];
            uint32_t a1 = xh32[(wr + 8) * 20 + s * 8 + lb];
            uint32_t a2 = xh32[wr * 20 + s * 8 + 4 + lb];
            uint32_t a3 = xh32[(wr + 8) * 20 + s * 8 + 4 + lb];
#pragma unroll
            for (int j = 0; j < 8; j++) {
                uint32_t b0 = csA[(j * 8 + la) * 20 + s * 8 + lb];
                uint32_t b1 = csA[(j * 8 + la) * 20 + s * 8 + 4 + lb];
                mma16(acc[j], a0, a1, a2, a3, b0, b1);
            }
        }
    }
    __syncthreads();

    float vA[8][2], vB[8][2];
#pragma unroll
    for (int j = 0; j < 8; j++)
#pragma unroll
        for (int e = 0; e < 2; e++) {
            int col = j * 8 + lb * 2 + e;
            float s = scf[col], h = shf[col];
            vA[j][e] = acc[j][e]     * s + h;
            vB[j][e] = acc[j][2 + e] * s + h;
        }

    float mA = -1e30f, mB = -1e30f;
#pragma unroll
    for (int j = 0; j < 8; j++)
#pragma unroll
        for (int e = 0; e < 2; e++) { mA = fmaxf(mA, vA[j][e]); mB = fmaxf(mB, vB[j][e]); }
    mA = fmaxf(mA, __shfl_xor_sync(0xffffffffu, mA, 1));
    mA = fmaxf(mA, __shfl_xor_sync(0xffffffffu, mA, 2));
    mB = fmaxf(mB, __shfl_xor_sync(0xffffffffu, mB, 1));
    mB = fmaxf(mB, __shfl_xor_sync(0xffffffffu, mB, 2));
    float sA = 0.0f, sB = 0.0f;
#pragma unroll
    for (int j = 0; j < 8; j++)
#pragma unroll
        for (int e = 0; e < 2; e++) {
            vA[j][e] = __expf(vA[j][e] - mA); sA += vA[j][e];
            vB[j][e] = __expf(vB[j][e] - mB); sB += vB[j][e];
        }
    sA += __shfl_xor_sync(0xffffffffu, sA, 1);
    sA += __shfl_xor_sync(0xffffffffu, sA, 2);
    sB += __shfl_xor_sync(0xffffffffu, sB, 1);
    sB += __shfl_xor_sync(0xffffffffu, sB, 2);
    float invA = 1.0f / sA, invB = 1.0f / sB;

    float csum[8][2];
#pragma unroll
    for (int j = 0; j < 8; j++)
#pragma unroll
        for (int e = 0; e < 2; e++) {
            vA[j][e] *= invA;
            vB[j][e] *= invB;
            csum[j][e] = vA[j][e] + vB[j][e];
        }

#pragma unroll
    for (int j = 0; j < 8; j++)
#pragma unroll
        for (int e = 0; e < 2; e++) {
            csum[j][e] += __shfl_xor_sync(0xffffffffu, csum[j][e], 4);
            csum[j][e] += __shfl_xor_sync(0xffffffffu, csum[j][e], 8);
            csum[j][e] += __shfl_xor_sync(0xffffffffu, csum[j][e], 16);
        }
    if (la == 0) {
#pragma unroll
        for (int j = 0; j < 8; j++)
#pragma unroll
            for (int e = 0; e < 2; e++)
                red[w * 64 + j * 8 + lb * 2 + e] = csum[j][e];
    }
    __syncthreads();
    if (tid < 64) {
        float s = 0.0f;
#pragma unroll
        for (int q = 0; q < 8; q++) s += red[q * 64 + tid];
        atomicAdd(&g_asum[(row0 >> 12) * Kk + tid], s);
    }

    uint16_t* hb = (uint16_t*)sm;
    const int bb  = row0 >> 12;
    const int r0n = row0 & (Nn - 1);
#pragma unroll
    for (int p = 0; p < 2; p++) {
        __syncthreads();
        if ((w >> 2) == p) {
            int wl = w & 3;
            int lA = wl * 16 + la, lB = lA + 8;
#pragma unroll
            for (int j = 0; j < 8; j++) {
                *(uint32_t*)&hb[lA * 74 + j * 8 + lb * 2] = h2pack(vA[j][0], vA[j][1]);
                *(uint32_t*)&hb[lB * 74 + j * 8 + lb * 2] = h2pack(vB[j][0], vB[j][1]);
            }
        }
        __syncthreads();
        int k = tid >> 2, sg2 = tid & 3;
        uint32_t o[8];
#pragma unroll
        for (int q = 0; q < 8; q++) {
            uint32_t lo = hb[(sg2 * 16 + 2 * q)     * 74 + k];
            uint32_t hi = hb[(sg2 * 16 + 2 * q + 1) * 74 + k];
            o[q] = lo | (hi << 16);
        }
        __half* dst = g_ah + ((size_t)(bb * Kk + k)) * Nn + r0n + p * 64 + sg2 * 16;
        *(uint4*)dst       = make_uint4(o[0], o[1], o[2], o[3]);
        *(uint4*)(dst + 8) = make_uint4(o[4], o[5], o[6], o[7]);
    }
}

// ---------------------------------------------------------------------------
// k2: vlad partials. 256 thr (8 warps), tile 128d x 64k, n-chunk 32,
// 3-stage cp.async. Grid (4 d-tiles, 32 b, NSPLIT) = 512 blocks.
// x smem tile [32 n][128 d] halves, row stride 272B (LDSM conflict-free:
// 272/4 = 68 == 4 mod 32). ah tile [64 k][80B] as before.
// ---------------------------------------------------------------------------
#define K2A_OFF  8704              // 32 * 272
#define K2_STAGE 13824             // x 8704 + ah 5120
#define K2_SMEM  41472

__device__ __forceinline__ void k2_issue(uint32_t sbase, const __half* xr,
                                         const __half* ar, int c, int tid) {
    if (c < Nn / NSPLIT / 32) {
        uint32_t st = sbase + (c % 3) * K2_STAGE;
        int n0 = c * 32;
        // x: 32 rows x 256B = 512 x 16B ops / 256 thr = 2 each
#pragma unroll
        for (int p = 0; p < 2; p++) {
            int id = p * 256 + tid;
            int xrow = id >> 4, xsg = id & 15;
            CP16(st + xrow * 272 + xsg * 16,
                 xr + (size_t)(n0 + xrow) * Dd + xsg * 8);
        }
        // ah: 64 rows x 64B = 256 x 16B ops / 256 thr = 1 each
        {
            int arow = tid >> 2, asg = tid & 3;
            CP16(st + K2A_OFF + arow * 80 + asg * 16,
                 ar + (size_t)arow * Nn + n0 + asg * 8);
        }
    }
    CP_COMMIT();
}

__global__ __launch_bounds__(256) void k2_vlad()
{
    extern __shared__ __align__(16) char sm[];
    const uint32_t sbase = smem_u32(sm);

    const int tid  = threadIdx.x;
    const int lane = tid & 31;
    const int w    = tid >> 5;             // 0..7: d rows w*16..w*16+15
    const int la   = lane >> 2;
    const int lb   = lane & 3;
    const int b    = blockIdx.y;
    const int d0   = blockIdx.x * 128;
    const int s    = blockIdx.z;
    const int nbase = s * (Nn / NSPLIT);

    const __half* xr = g_xh + ((size_t)(b * Nn + nbase)) * Dd + d0;
    const __half* ar = g_ah + ((size_t)(b * Kk)) * Nn + nbase;

    float acc[8][4];
#pragma unroll
    for (int j = 0; j < 8; j++)
#pragma unroll
        for (int q = 0; q < 4; q++) acc[j][q] = 0.0f;

    k2_issue(sbase, xr, ar, 0, tid);
    k2_issue(sbase, xr, ar, 1, tid);

    const int lq = lane >> 3, lr = lane & 7;
    const uint32_t xoff = ((lq >> 1) * 8 + lr) * 272 + (w * 16 + (lq & 1) * 8) * 2;

    const int L = Nn / NSPLIT / 32;
    for (int c = 0; c < L; c++) {
        __syncthreads();
        k2_issue(sbase, xr, ar, c + 2, tid);
        CP_WAIT2();
        __syncthreads();

        const uint32_t xbase = sbase + (c % 3) * K2_STAGE + xoff;
        const uint32_t* asA = (const uint32_t*)(sm + (c % 3) * K2_STAGE + K2A_OFF);
#pragma unroll
        for (int ss = 0; ss < 2; ss++) {
            uint32_t a0, a1, a2, a3;
            ldsm4t(a0, a1, a2, a3, xbase + ss * 16 * 272);
#pragma unroll
            for (int j = 0; j < 8; j++) {
                uint32_t b0 = asA[(j * 8 + la) * 20 + ss * 8 + lb];
                uint32_t b1 = asA[(j * 8 + la) * 20 + ss * 8 + 4 + lb];
                mma16(acc[j], a0, a1, a2, a3, b0, b1);
            }
        }
    }

    float* vp = g_vpart + ((size_t)s * Bb + b) * Kk * Dd;
    const int gdA = d0 + w * 16 + la;
    const int gdB = gdA + 8;
#pragma unroll
    for (int j = 0; j < 8; j++)
#pragma unroll
        for (int e = 0; e < 2; e++) {
            int col = j * 8 + lb * 2 + e;
            vp[(size_t)col * Dd + gdA] = acc[j][e];
            vp[(size_t)col * Dd + gdB] = acc[j][2 + e];
        }
}

// ---------------------------------------------------------------------------
// k3: sum 4 partial planes, subtract a_sum*clusters2, intra-normalize, out.
// ---------------------------------------------------------------------------
__global__ __launch_bounds__(128) void k3_colnorm(const float* __restrict__ c2,
                                                  float* __restrict__ out)
{
    const int bk = blockIdx.x;
    const int b = bk >> 6;
    const int k = bk & 63;
    const int tid = threadIdx.x;
    const size_t SP = (size_t)Bb * Kk * Dd;

    const float a = g_asum[bk];
    const float* vr = g_vpart + (size_t)bk * Dd;

    float v[4];
    float ss = 0.0f;
#pragma unroll
    for (int p = 0; p < 4; p++) {
        int d = tid + p * 128;
        float t = (vr[d] + vr[d + SP]) + (vr[d + 2 * SP] + vr[d + 3 * SP])
                - a * c2[(size_t)d * Kk + k];
        v[p] = t;
        ss += t * t;
    }
#pragma unroll
    for (int o = 16; o; o >>= 1) ss += __shfl_xor_sync(0xffffffffu, ss, o);

    __shared__ float sred[4];
    if ((tid & 31) == 0) sred[tid >> 5] = ss;
    __syncthreads();
    float tot = sred[0] + sred[1] + sred[2] + sred[3];
    float inv = 1.0f / fmaxf(sqrtf(tot), 1e-12f);
    if (tid == 0) atomicAdd(&g_gnormsq[b], tot * inv * inv);

    float* ob = out + (size_t)b * (Dd * Kk);
#pragma unroll
    for (int p = 0; p < 4; p++) {
        int d = tid + p * 128;
        ob[(size_t)d * Kk + k] = v[p] * inv;
    }
}

// ---------------------------------------------------------------------------
__global__ void k4_scale(float* __restrict__ out)
{
    int idx = blockIdx.x * 256 + threadIdx.x;
    int b = idx >> 15;
    out[idx] *= 1.0f / fmaxf(sqrtf(g_gnormsq[b]), 1e-12f);
}

// ---------------------------------------------------------------------------
extern "C" void kernel_launch(void* const* d_in, const int* in_sizes, int n_in,
                              void* d_out, int out_size)
{
    const float* x        = (const float*)d_in[0];
    const float* clusters = (const float*)d_in[1];
    const float* c2       = (const float*)d_in[2];
    const float* bnw      = (const float*)d_in[3];
    const float* bnb      = (const float*)d_in[4];
    const float* rm       = (const float*)d_in[5];
    const float* rv       = (const float*)d_in[6];
    float* out = (float*)d_out;

    cudaFuncSetAttribute(k1_logits_softmax,
                         cudaFuncAttributeMaxDynamicSharedMemorySize, K1_SMEM);
    cudaFuncSetAttribute(k2_vlad,
                         cudaFuncAttributeMaxDynamicSharedMemorySize, K2_SMEM);

    k0_init<<<8, 256>>>();
    kC<<<32, 256>>>(clusters);
    k1_logits_softmax<<<(Bb * Nn) / 128, 256, K1_SMEM>>>(x, bnw, bnb, rm, rv);
    dim3 g2(Dd / 128, Bb, NSPLIT);
    k2_vlad<<<g2, 256, K2_SMEM>>>();
    k3_colnorm<<<Bb * Kk, 128>>>(c2, out);
    k4_scale<<<(Bb * Dd * Kk) / 256, 256>>>(out);
}

// round 17
// speedup vs baseline: 1.0398x; 1.0398x over previous
#include <cuda_runtime.h>
#include <cuda_fp16.h>
#include <math.h>
#include <stdint.h>

// B=32, N=4096, D=512, K=64
#define Bb 32
#define Nn 4096
#define Dd 512
#define Kk 64
#define NSPLIT 4

__device__ __half g_xh[(size_t)Bb * Nn * Dd];              // x as half, [n][d] (written by k1)
__device__ __half g_ch[(size_t)Kk * Dd];                   // clusters^T half [k][d]
__device__ __half g_ah[(size_t)Bb * Kk * Nn];              // assignment^T half [b][k][n]
__device__ float  g_vpart[(size_t)NSPLIT * Bb * Kk * Dd];  // vlad partials [s,b,k,d]
__device__ float  g_asum_part[1024 * Kk];                  // per-k1-block a_sum partials
__device__ float  g_gnpart[Bb * 4];                        // per-(b,kgroup) gnormsq partials

__device__ __forceinline__ uint32_t h2pack(float lo, float hi) {
    __half2 h = __floats2half2_rn(lo, hi);
    return *(uint32_t*)&h;
}

__device__ __forceinline__ void mma16(float* c, uint32_t a0, uint32_t a1,
                                      uint32_t a2, uint32_t a3,
                                      uint32_t b0, uint32_t b1) {
    asm volatile(
        "mma.sync.aligned.m16n8k16.row.col.f32.f16.f16.f32 "
        "{%0,%1,%2,%3},{%4,%5,%6,%7},{%8,%9},{%0,%1,%2,%3};\n"
        : "+f"(c[0]), "+f"(c[1]), "+f"(c[2]), "+f"(c[3])
        : "r"(a0), "r"(a1), "r"(a2), "r"(a3), "r"(b0), "r"(b1));
}

__device__ __forceinline__ void ldsm4t(uint32_t& r0, uint32_t& r1,
                                       uint32_t& r2, uint32_t& r3, uint32_t a) {
    asm volatile(
        "ldmatrix.sync.aligned.m8n8.x4.trans.shared.b16 {%0,%1,%2,%3}, [%4];"
        : "=r"(r0), "=r"(r1), "=r"(r2), "=r"(r3) : "r"(a));
}

__device__ __forceinline__ uint32_t smem_u32(const void* p) {
    uint32_t a;
    asm("{ .reg .u64 t; cvta.to.shared.u64 t, %1; cvt.u32.u64 %0, t; }"
        : "=r"(a) : "l"(p));
    return a;
}

#define CP16(dst, src) \
    asm volatile("cp.async.cg.shared.global [%0], [%1], 16;\n" \
                 :: "r"(dst), "l"(src) : "memory")
#define CP_COMMIT() asm volatile("cp.async.commit_group;\n" ::: "memory")
#define CP_WAIT1()  asm volatile("cp.async.wait_group 1;\n" ::: "memory")
#define CP_WAIT2()  asm volatile("cp.async.wait_group 2;\n" ::: "memory")

// ---------------------------------------------------------------------------
// kC: clusters [d][k] fp32 -> g_ch [k][d] half
// ---------------------------------------------------------------------------
__global__ __launch_bounds__(256) void kC(const float* __restrict__ clusters) {
    int idx4 = (blockIdx.x * 256 + threadIdx.x) * 4;
    int d = idx4 >> 6, k = idx4 & 63;
    float4 c = *(const float4*)&clusters[idx4];
    g_ch[(size_t)(k + 0) * Dd + d] = __float2half_rn(c.x);
    g_ch[(size_t)(k + 1) * Dd + d] = __float2half_rn(c.y);
    g_ch[(size_t)(k + 2) * Dd + d] = __float2half_rn(c.z);
    g_ch[(size_t)(k + 3) * Dd + d] = __float2half_rn(c.w);
}

// ---------------------------------------------------------------------------
// k1: x fp32 in (2-stage cp.async) -> fp16 convert (smem + g_xh out),
// fp16 MMA + BN + softmax + assignment^T(half) + a_sum partial store.
// ---------------------------------------------------------------------------
#define K1F_CS   18432
#define K1F_ST   23552
#define K1_XSH   47104
#define K1_SCF   57344
#define K1_SHF   57600
#define K1_RED   57856
#define K1_SMEM  59904

__device__ __forceinline__ void k1_issue(uint32_t sbase, const float* xg,
                                         int c, int tid) {
    if (c < 16) {
        uint32_t st = sbase + (c & 1) * K1F_ST;
        int d0 = c * 32;
#pragma unroll
        for (int p = 0; p < 4; p++) {
            int id = p * 256 + tid;
            int row = id >> 3, sq = id & 7;
            CP16(st + row * 144 + sq * 16,
                 xg + (size_t)row * Dd + d0 + sq * 4);
        }
        {
            int row = tid >> 2, sq = tid & 3;
            CP16(st + K1F_CS + row * 80 + sq * 16,
                 g_ch + (size_t)row * Dd + d0 + sq * 8);
        }
    }
    CP_COMMIT();
}

__global__ __launch_bounds__(256) void k1_logits_softmax(
    const float* __restrict__ x,
    const float* __restrict__ bnw,
    const float* __restrict__ bnb,
    const float* __restrict__ rm,
    const float* __restrict__ rv)
{
    extern __shared__ __align__(16) char sm[];
    float* scf = (float*)(sm + K1_SCF);
    float* shf = (float*)(sm + K1_SHF);
    float* red = (float*)(sm + K1_RED);
    uint32_t* xh32 = (uint32_t*)(sm + K1_XSH);
    const uint32_t sbase = smem_u32(sm);

    const int tid  = threadIdx.x;
    const int lane = tid & 31;
    const int w    = tid >> 5;
    const int la   = lane >> 2;
    const int lb   = lane & 3;
    const int row0 = blockIdx.x * 128;

    if (tid < 64) {
        float istd = rsqrtf(rv[tid] + 1e-5f);
        float s = bnw[tid] * istd;
        scf[tid] = s;
        shf[tid] = bnb[tid] - rm[tid] * s;
    }

    const float* xg = x + (size_t)row0 * Dd;

    float acc[8][4];
#pragma unroll
    for (int j = 0; j < 8; j++)
#pragma unroll
        for (int q = 0; q < 4; q++) acc[j][q] = 0.0f;

    k1_issue(sbase, xg, 0, tid);

    const int wr = w * 16 + la;
    const int crow = tid >> 1;
    const int ch   = tid & 1;

    for (int c = 0; c < 16; c++) {
        __syncthreads();
        k1_issue(sbase, xg, c + 1, tid);
        CP_WAIT1();
        __syncthreads();

        {
            const char* stx = sm + (c & 1) * K1F_ST;
            const float4* src = (const float4*)(stx + crow * 144 + ch * 64);
            float4 v0 = src[0], v1 = src[1], v2 = src[2], v3 = src[3];
            uint32_t wv[8];
            wv[0] = h2pack(v0.x, v0.y); wv[1] = h2pack(v0.z, v0.w);
            wv[2] = h2pack(v1.x, v1.y); wv[3] = h2pack(v1.z, v1.w);
            wv[4] = h2pack(v2.x, v2.y); wv[5] = h2pack(v2.z, v2.w);
            wv[6] = h2pack(v3.x, v3.y); wv[7] = h2pack(v3.z, v3.w);
            *(uint4*)&xh32[crow * 20 + ch * 8]     = make_uint4(wv[0], wv[1], wv[2], wv[3]);
            *(uint4*)&xh32[crow * 20 + ch * 8 + 4] = make_uint4(wv[4], wv[5], wv[6], wv[7]);
            __half* gd = g_xh + (size_t)(row0 + crow) * Dd + c * 32 + ch * 16;
            *(uint4*)gd       = make_uint4(wv[0], wv[1], wv[2], wv[3]);
            *(uint4*)(gd + 8) = make_uint4(wv[4], wv[5], wv[6], wv[7]);
        }
        __syncthreads();

        const uint32_t* csA = (const uint32_t*)(sm + (c & 1) * K1F_ST + K1F_CS);
#pragma unroll
        for (int s = 0; s < 2; s++) {
            uint32_t a0 = xh32[wr * 20 + s * 8 + lb];
            uint32_t a1 = xh32[(wr + 8) * 20 + s * 8 + lb];
            uint32_t a2 = xh32[wr * 20 + s * 8 + 4 + lb];
            uint32_t a3 = xh32[(wr + 8) * 20 + s * 8 + 4 + lb];
#pragma unroll
            for (int j = 0; j < 8; j++) {
                uint32_t b0 = csA[(j * 8 + la) * 20 + s * 8 + lb];
                uint32_t b1 = csA[(j * 8 + la) * 20 + s * 8 + 4 + lb];
                mma16(acc[j], a0, a1, a2, a3, b0, b1);
            }
        }
    }
    __syncthreads();

    float vA[8][2], vB[8][2];
#pragma unroll
    for (int j = 0; j < 8; j++)
#pragma unroll
        for (int e = 0; e < 2; e++) {
            int col = j * 8 + lb * 2 + e;
            float s = scf[col], h = shf[col];
            vA[j][e] = acc[j][e]     * s + h;
            vB[j][e] = acc[j][2 + e] * s + h;
        }

    float mA = -1e30f, mB = -1e30f;
#pragma unroll
    for (int j = 0; j < 8; j++)
#pragma unroll
        for (int e = 0; e < 2; e++) { mA = fmaxf(mA, vA[j][e]); mB = fmaxf(mB, vB[j][e]); }
    mA = fmaxf(mA, __shfl_xor_sync(0xffffffffu, mA, 1));
    mA = fmaxf(mA, __shfl_xor_sync(0xffffffffu, mA, 2));
    mB = fmaxf(mB, __shfl_xor_sync(0xffffffffu, mB, 1));
    mB = fmaxf(mB, __shfl_xor_sync(0xffffffffu, mB, 2));
    float sA = 0.0f, sB = 0.0f;
#pragma unroll
    for (int j = 0; j < 8; j++)
#pragma unroll
        for (int e = 0; e < 2; e++) {
            vA[j][e] = __expf(vA[j][e] - mA); sA += vA[j][e];
            vB[j][e] = __expf(vB[j][e] - mB); sB += vB[j][e];
        }
    sA += __shfl_xor_sync(0xffffffffu, sA, 1);
    sA += __shfl_xor_sync(0xffffffffu, sA, 2);
    sB += __shfl_xor_sync(0xffffffffu, sB, 1);
    sB += __shfl_xor_sync(0xffffffffu, sB, 2);
    float invA = 1.0f / sA, invB = 1.0f / sB;

    float csum[8][2];
#pragma unroll
    for (int j = 0; j < 8; j++)
#pragma unroll
        for (int e = 0; e < 2; e++) {
            vA[j][e] *= invA;
            vB[j][e] *= invB;
            csum[j][e] = vA[j][e] + vB[j][e];
        }

#pragma unroll
    for (int j = 0; j < 8; j++)
#pragma unroll
        for (int e = 0; e < 2; e++) {
            csum[j][e] += __shfl_xor_sync(0xffffffffu, csum[j][e], 4);
            csum[j][e] += __shfl_xor_sync(0xffffffffu, csum[j][e], 8);
            csum[j][e] += __shfl_xor_sync(0xffffffffu, csum[j][e], 16);
        }
    if (la == 0) {
#pragma unroll
        for (int j = 0; j < 8; j++)
#pragma unroll
            for (int e = 0; e < 2; e++)
                red[w * 64 + j * 8 + lb * 2 + e] = csum[j][e];
    }
    __syncthreads();
    if (tid < 64) {
        float s = 0.0f;
#pragma unroll
        for (int q = 0; q < 8; q++) s += red[q * 64 + tid];
        g_asum_part[blockIdx.x * 64 + tid] = s;   // no atomics, no init
    }

    uint16_t* hb = (uint16_t*)sm;
    const int bb  = row0 >> 12;
    const int r0n = row0 & (Nn - 1);
#pragma unroll
    for (int p = 0; p < 2; p++) {
        __syncthreads();
        if ((w >> 2) == p) {
            int wl = w & 3;
            int lA = wl * 16 + la, lB = lA + 8;
#pragma unroll
            for (int j = 0; j < 8; j++) {
                *(uint32_t*)&hb[lA * 74 + j * 8 + lb * 2] = h2pack(vA[j][0], vA[j][1]);
                *(uint32_t*)&hb[lB * 74 + j * 8 + lb * 2] = h2pack(vB[j][0], vB[j][1]);
            }
        }
        __syncthreads();
        int k = tid >> 2, sg2 = tid & 3;
        uint32_t o[8];
#pragma unroll
        for (int q = 0; q < 8; q++) {
            uint32_t lo = hb[(sg2 * 16 + 2 * q)     * 74 + k];
            uint32_t hi = hb[(sg2 * 16 + 2 * q + 1) * 74 + k];
            o[q] = lo | (hi << 16);
        }
        __half* dst = g_ah + ((size_t)(bb * Kk + k)) * Nn + r0n + p * 64 + sg2 * 16;
        *(uint4*)dst       = make_uint4(o[0], o[1], o[2], o[3]);
        *(uint4*)(dst + 8) = make_uint4(o[4], o[5], o[6], o[7]);
    }
}

// ---------------------------------------------------------------------------
// k2: vlad partials (unchanged from R15 winner shape: 128 thr, 64d x 64k,
// NSPLIT=4, 3-stage cp.async, ldmatrix.trans A).
// ---------------------------------------------------------------------------
#define K2A_OFF  4608
#define K2_STAGE 9728
#define K2_SMEM  29184

__device__ __forceinline__ void k2_issue(uint32_t sbase, const __half* xr,
                                         const __half* ar, int c, int tid) {
    if (c < Nn / NSPLIT / 32) {
        uint32_t st = sbase + (c % 3) * K2_STAGE;
        int n0 = c * 32;
#pragma unroll
        for (int p = 0; p < 2; p++) {
            int id = p * 128 + tid;
            int xrow = id >> 3, xsg = id & 7;
            CP16(st + xrow * 144 + xsg * 16,
                 xr + (size_t)(n0 + xrow) * Dd + xsg * 8);
            int arow = id >> 2, asg = id & 3;
            CP16(st + K2A_OFF + arow * 80 + asg * 16,
                 ar + (size_t)arow * Nn + n0 + asg * 8);
        }
    }
    CP_COMMIT();
}

__global__ __launch_bounds__(128) void k2_vlad()
{
    extern __shared__ __align__(16) char sm[];
    const uint32_t sbase = smem_u32(sm);

    const int tid  = threadIdx.x;
    const int lane = tid & 31;
    const int w    = tid >> 5;
    const int la   = lane >> 2;
    const int lb   = lane & 3;
    const int b    = blockIdx.y;
    const int d0   = blockIdx.x * 64;
    const int s    = blockIdx.z;
    const int nbase = s * (Nn / NSPLIT);

    const __half* xr = g_xh + ((size_t)(b * Nn + nbase)) * Dd + d0;
    const __half* ar = g_ah + ((size_t)(b * Kk)) * Nn + nbase;

    float acc[8][4];
#pragma unroll
    for (int j = 0; j < 8; j++)
#pragma unroll
        for (int q = 0; q < 4; q++) acc[j][q] = 0.0f;

    k2_issue(sbase, xr, ar, 0, tid);
    k2_issue(sbase, xr, ar, 1, tid);

    const int lq = lane >> 3, lr = lane & 7;
    const uint32_t xoff = ((lq >> 1) * 8 + lr) * 144 + (w * 16 + (lq & 1) * 8) * 2;

    const int L = Nn / NSPLIT / 32;
    for (int c = 0; c < L; c++) {
        __syncthreads();
        k2_issue(sbase, xr, ar, c + 2, tid);
        CP_WAIT2();
        __syncthreads();

        const uint32_t xbase = sbase + (c % 3) * K2_STAGE + xoff;
        const uint32_t* asA = (const uint32_t*)(sm + (c % 3) * K2_STAGE + K2A_OFF);
#pragma unroll
        for (int ss = 0; ss < 2; ss++) {
            uint32_t a0, a1, a2, a3;
            ldsm4t(a0, a1, a2, a3, xbase + ss * 16 * 144);
#pragma unroll
            for (int j = 0; j < 8; j++) {
                uint32_t b0 = asA[(j * 8 + la) * 20 + ss * 8 + lb];
                uint32_t b1 = asA[(j * 8 + la) * 20 + ss * 8 + 4 + lb];
                mma16(acc[j], a0, a1, a2, a3, b0, b1);
            }
        }
    }

    float* vp = g_vpart + ((size_t)s * Bb + b) * Kk * Dd;
    const int gdA = d0 + w * 16 + la;
    const int gdB = gdA + 8;
#pragma unroll
    for (int j = 0; j < 8; j++)
#pragma unroll
        for (int e = 0; e < 2; e++) {
            int col = j * 8 + lb * 2 + e;
            vp[(size_t)col * Dd + gdA] = acc[j][e];
            vp[(size_t)col * Dd + gdB] = acc[j][2 + e];
        }
}

// ---------------------------------------------------------------------------
// k3: per (b, 16-k group): reduce a_sum partials, sum 4 vpart planes,
// subtract a_sum*c2, intra-normalize over D, write COALESCED via smem
// transpose, store per-group gnormsq partial. Grid (4, 32), 256 thr.
// ---------------------------------------------------------------------------
__global__ __launch_bounds__(256) void k3_colnorm(const float* __restrict__ c2,
                                                  float* __restrict__ out)
{
    __shared__ float ts[16][516];
    __shared__ float sa[16][17];
    __shared__ float av[16];
    __shared__ float siv[16];
    __shared__ float sgn[16];

    const int tid = threadIdx.x;
    const int kg  = blockIdx.x;       // 0..3
    const int b   = blockIdx.y;       // 0..31
    const size_t SP = (size_t)Bb * Kk * Dd;

    // --- reduce a_sum partials: a[kt] = sum over 32 k1-blocks of this batch ---
    {
        int j2 = tid >> 4, kt = tid & 15;
        float s = g_asum_part[(size_t)(b * 32 + j2) * 64 + kg * 16 + kt]
                + g_asum_part[(size_t)(b * 32 + j2 + 16) * 64 + kg * 16 + kt];
        sa[j2][kt] = s;
    }
    __syncthreads();
    if (tid < 16) {
        float a = 0.0f;
#pragma unroll
        for (int j2 = 0; j2 < 16; j2++) a += sa[j2][tid];
        av[tid] = a;
    }
    __syncthreads();

    // --- main: per (kt) column over all 512 d ---
    const int kt = tid >> 4;          // 0..15
    const int dp = tid & 15;          // 0..15
    const int kk = kg * 16 + kt;      // global k
    const float* vr = g_vpart + ((size_t)(b * 64 + kk)) * Dd;
    const float a = av[kt];

    float ss = 0.0f;
#pragma unroll
    for (int i = 0; i < 8; i++) {
        int d0 = dp * 4 + i * 64;
        float4 p0 = *(const float4*)&vr[d0];
        float4 p1 = *(const float4*)&vr[d0 + SP];
        float4 p2 = *(const float4*)&vr[d0 + 2 * SP];
        float4 p3 = *(const float4*)&vr[d0 + 3 * SP];
        float t0 = (p0.x + p1.x) + (p2.x + p3.x) - a * c2[(size_t)(d0 + 0) * Kk + kk];
        float t1 = (p0.y + p1.y) + (p2.y + p3.y) - a * c2[(size_t)(d0 + 1) * Kk + kk];
        float t2 = (p0.z + p1.z) + (p2.z + p3.z) - a * c2[(size_t)(d0 + 2) * Kk + kk];
        float t3 = (p0.w + p1.w) + (p2.w + p3.w) - a * c2[(size_t)(d0 + 3) * Kk + kk];
        ss += t0 * t0 + t1 * t1 + t2 * t2 + t3 * t3;
        *(float4*)&ts[kt][d0] = make_float4(t0, t1, t2, t3);
    }
    // reduce ss within the 16-lane kt group
#pragma unroll
    for (int o = 1; o < 16; o <<= 1) ss += __shfl_xor_sync(0xffffffffu, ss, o);
    float inv = 1.0f / fmaxf(sqrtf(ss), 1e-12f);
    if (dp == 0) { siv[kt] = inv; sgn[kt] = ss * inv * inv; }
    __syncthreads();
    if (tid == 0) {
        float g = 0.0f;
#pragma unroll
        for (int q = 0; q < 16; q++) g += sgn[q];
        g_gnpart[b * 4 + kg] = g;
    }

    // --- coalesced write: out[b][d*64 + kg*16 + kq] ---
    float* ob = out + (size_t)b * (Dd * Kk) + kg * 16;
    const int kq = tid & 15;
    const int dd = tid >> 4;
    const float invk = siv[kq];
#pragma unroll
    for (int pass = 0; pass < 32; pass++) {
        int d = pass * 16 + dd;
        ob[(size_t)d * Kk + kq] = ts[kq][d] * invk;
    }
}

// ---------------------------------------------------------------------------
// k4: final global L2 scale per batch (gnormsq = sum of 4 partials)
// ---------------------------------------------------------------------------
__global__ void k4_scale(float* __restrict__ out)
{
    int idx = blockIdx.x * 256 + threadIdx.x;
    int b = idx >> 15;
    float g = (g_gnpart[b * 4 + 0] + g_gnpart[b * 4 + 1])
            + (g_gnpart[b * 4 + 2] + g_gnpart[b * 4 + 3]);
    out[idx] *= 1.0f / fmaxf(sqrtf(g), 1e-12f);
}

// ---------------------------------------------------------------------------
extern "C" void kernel_launch(void* const* d_in, const int* in_sizes, int n_in,
                              void* d_out, int out_size)
{
    const float* x        = (const float*)d_in[0];
    const float* clusters = (const float*)d_in[1];
    const float* c2       = (const float*)d_in[2];
    const float* bnw      = (const float*)d_in[3];
    const float* bnb      = (const float*)d_in[4];
    const float* rm       = (const float*)d_in[5];
    const float* rv       = (const float*)d_in[6];
    float* out = (float*)d_out;

    cudaFuncSetAttribute(k1_logits_softmax,
                         cudaFuncAttributeMaxDynamicSharedMemorySize, K1_SMEM);

    kC<<<32, 256>>>(clusters);
    k1_logits_softmax<<<(Bb * Nn) / 128, 256, K1_SMEM>>>(x, bnw, bnb, rm, rv);
    dim3 g2(Dd / 64, Bb, NSPLIT);
    k2_vlad<<<g2, 128, K2_SMEM>>>();
    dim3 g3(4, Bb);
    k3_colnorm<<<g3, 256>>>(c2, out);
    k4_scale<<<(Bb * Dd * Kk) / 256, 256>>>(out);
}